// round 3
// baseline (speedup 1.0000x reference)
#include <cuda_runtime.h>
#include <cstddef>

// ---------------------------------------------------------------------------
// EdgeTransition, algebraically reduced + fully fused.
//   nb   = node @ w_init + b_init                       [512,128]
//   P0i  = nb @ W0[128:256] + b0     P0j = nb @ W0[256:384]      [512,384]
//   Pfi  = nb @ Wf[128:256] + bf     Pfj = nb @ Wf[256:384]      [512,128]
//   per edge tile (64 rows, same i):
//     t0 = relu(edge @ W0[0:128] + P0i[i] + P0j[j])
//     t1 = relu(t0 @ W1 + b1)             (chunked, never materialized fully)
//     o  = t1 @ Wf + edge @ Wf[0:128] + Pfi[i] + Pfj[j]
//     out = LayerNorm(o) * g + b
// ---------------------------------------------------------------------------

#define NSEQ   512
#define BIASD  128
#define HID    384
#define EOUT   128
#define TM     64

// strides (floats) with +4 pad to break bank conflicts on A reads
#define S_ES   132
#define S_T0   388
#define S_RS   68

__device__ float g_nb [NSEQ * BIASD];
__device__ float g_p0i[NSEQ * HID];
__device__ float g_p0j[NSEQ * HID];
__device__ float g_pfi[NSEQ * EOUT];
__device__ float g_pfj[NSEQ * EOUT];

typedef unsigned long long u64;

__device__ __forceinline__ u64 pk(float x, float y) {
    u64 r; asm("mov.b64 %0, {%1, %2};" : "=l"(r) : "f"(x), "f"(y)); return r;
}
__device__ __forceinline__ void upk(u64 r, float& x, float& y) {
    asm("mov.b64 {%0, %1}, %2;" : "=f"(x), "=f"(y) : "l"(r));
}
__device__ __forceinline__ void fma2(u64& d, u64 a, u64 b) {
    asm("fma.rn.f32x2 %0, %1, %2, %0;" : "+l"(d) : "l"(a), "l"(b));
}

// ---------------------------------------------------------------------------
// nb = node_embed @ w_init + b_init
__global__ void nb_kernel(const float* __restrict__ node,
                          const float* __restrict__ w_init,
                          const float* __restrict__ b_init) {
    __shared__ float xs[256];
    int i = blockIdx.x, t = threadIdx.x;   // 128 threads
    xs[t]       = node[i * 256 + t];
    xs[t + 128] = node[i * 256 + 128 + t];
    __syncthreads();
    float acc = b_init[t];
#pragma unroll 8
    for (int k = 0; k < 256; k++) acc += xs[k] * w_init[k * 128 + t];
    g_nb[i * 128 + t] = acc;
}

// ---------------------------------------------------------------------------
// per-row bias tables
__global__ void pre_kernel(const float* __restrict__ w_t0,
                           const float* __restrict__ b_t0,
                           const float* __restrict__ w_fin,
                           const float* __restrict__ b_fin) {
    __shared__ float nbs[128];
    int i = blockIdx.x, t = threadIdx.x;   // 384 threads
    if (t < 128) nbs[t] = g_nb[i * 128 + t];
    __syncthreads();
    float a0 = b_t0[t], a1 = 0.f;
#pragma unroll 8
    for (int k = 0; k < 128; k++) {
        float v = nbs[k];
        a0 += v * w_t0[(128 + k) * HID + t];
        a1 += v * w_t0[(256 + k) * HID + t];
    }
    g_p0i[i * HID + t] = a0;
    g_p0j[i * HID + t] = a1;
    if (t < 128) {
        float f0 = b_fin[t], f1 = 0.f;
#pragma unroll 8
        for (int k = 0; k < 128; k++) {
            float v = nbs[k];
            f0 += v * w_fin[(128 + k) * EOUT + t];
            f1 += v * w_fin[(256 + k) * EOUT + t];
        }
        g_pfi[i * EOUT + t] = f0;
        g_pfj[i * EOUT + t] = f1;
    }
}

// ---------------------------------------------------------------------------
// 64x64 B tile loader: bs[k][n] = g[k*ldg + n]
__device__ __forceinline__ void load_b(const float* __restrict__ g, int ldg,
                                       float* __restrict__ bs, int tid) {
#pragma unroll
    for (int v = tid; v < 1024; v += 256) {
        int k = v >> 4, c = (v & 15) * 4;
        *(float4*)(bs + k * 64 + c) = *(const float4*)(g + (size_t)k * ldg + c);
    }
}

// 64x64x64 micro-GEMM, 4x4 per thread, packed f32x2 FMAs along n
__device__ __forceinline__ void gemm_tile(const float* __restrict__ A, int lda,
                                          const float* __restrict__ bs,
                                          int tx, int ty, u64 acc2[4][2]) {
    const float* a0p = A + (ty * 4 + 0) * lda;
    const float* a1p = A + (ty * 4 + 1) * lda;
    const float* a2p = A + (ty * 4 + 2) * lda;
    const float* a3p = A + (ty * 4 + 3) * lda;
    const float* bp0 = bs + tx * 4;
#pragma unroll 8
    for (int k = 0; k < 64; k++) {
        u64 b01 = *(const u64*)(bp0 + k * 64);
        u64 b23 = *(const u64*)(bp0 + k * 64 + 2);
        u64 aa0 = pk(a0p[k], a0p[k]);
        u64 aa1 = pk(a1p[k], a1p[k]);
        u64 aa2 = pk(a2p[k], a2p[k]);
        u64 aa3 = pk(a3p[k], a3p[k]);
        fma2(acc2[0][0], aa0, b01); fma2(acc2[0][1], aa0, b23);
        fma2(acc2[1][0], aa1, b01); fma2(acc2[1][1], aa1, b23);
        fma2(acc2[2][0], aa2, b01); fma2(acc2[2][1], aa2, b23);
        fma2(acc2[3][0], aa3, b01); fma2(acc2[3][1], aa3, b23);
    }
}

#define SMEM_FLOATS (TM * S_ES + TM * S_T0 + 64 * 64 + TM * S_RS)

__global__ void __launch_bounds__(256, 1)
fused_kernel(const float* __restrict__ edge,
             const float* __restrict__ w_t0,
             const float* __restrict__ w_t1,
             const float* __restrict__ b_t1,
             const float* __restrict__ w_fin,
             const float* __restrict__ ln_g,
             const float* __restrict__ ln_b,
             float* __restrict__ out) {
    extern __shared__ float sm[];
    float* es  = sm;                       // [64][132] edge tile, later o tile
    float* t0s = sm + TM * S_ES;           // [64][388]
    float* bs  = t0s + TM * S_T0;          // [64][64]
    float* rs  = bs + 64 * 64;             // [64][68]

    const int tile = blockIdx.x;           // 4096 tiles
    const int i    = tile >> 3;
    const int j0   = (tile & 7) << 6;
    const int tid  = threadIdx.x;
    const int tx   = tid & 15, ty = tid >> 4;

    // ---- load edge tile [64,128] ----
    {
        const float4* src = (const float4*)(edge + (size_t)(i * NSEQ + j0) * 128);
#pragma unroll
        for (int v = tid; v < 2048; v += 256) {
            int r = v >> 5, c = v & 31;
            *(float4*)(es + r * S_ES + c * 4) = src[r * 32 + c];
        }
    }
    __syncthreads();

    // ---- layer 0: t0 = relu(edge @ W0_top + P0i + P0j) ----
    for (int nc = 0; nc < 6; nc++) {
        const int n0 = nc * 64;
        u64 acc2[4][2] = {};
        for (int kc = 0; kc < 2; kc++) {
            load_b(w_t0 + (size_t)(kc * 64) * HID + n0, HID, bs, tid);
            __syncthreads();
            gemm_tile(es + kc * 64, S_ES, bs, tx, ty, acc2);
            __syncthreads();
        }
        const float4 pi = *(const float4*)(g_p0i + (size_t)i * HID + n0 + tx * 4);
#pragma unroll
        for (int r = 0; r < 4; r++) {
            int m = ty * 4 + r;
            float4 pj = *(const float4*)(g_p0j + (size_t)(j0 + m) * HID + n0 + tx * 4);
            float v0, v1, v2, v3;
            upk(acc2[r][0], v0, v1); upk(acc2[r][1], v2, v3);
            float* d = t0s + m * S_T0 + n0 + tx * 4;
            d[0] = fmaxf(v0 + pi.x + pj.x, 0.f);
            d[1] = fmaxf(v1 + pi.y + pj.y, 0.f);
            d[2] = fmaxf(v2 + pi.z + pj.z, 0.f);
            d[3] = fmaxf(v3 + pi.w + pj.w, 0.f);
        }
    }
    __syncthreads();

    // ---- layer 1 + final GEMM, t1 chunked (never materialized) ----
    u64 oacc2[2][4][2] = {};
    for (int kc2 = 0; kc2 < 6; kc2++) {
        const int K0 = kc2 * 64;
        u64 acc2[4][2] = {};
        for (int kc = 0; kc < 6; kc++) {
            load_b(w_t1 + (size_t)(kc * 64) * HID + K0, HID, bs, tid);
            __syncthreads();
            gemm_tile(t0s + kc * 64, S_T0, bs, tx, ty, acc2);
            __syncthreads();
        }
        {   // relu + b1 -> rs chunk [64,64]
            const float4 bb = *(const float4*)(b_t1 + K0 + tx * 4);
#pragma unroll
            for (int r = 0; r < 4; r++) {
                float v0, v1, v2, v3;
                upk(acc2[r][0], v0, v1); upk(acc2[r][1], v2, v3);
                float* d = rs + (ty * 4 + r) * S_RS + tx * 4;
                d[0] = fmaxf(v0 + bb.x, 0.f);
                d[1] = fmaxf(v1 + bb.y, 0.f);
                d[2] = fmaxf(v2 + bb.z, 0.f);
                d[3] = fmaxf(v3 + bb.w, 0.f);
            }
        }
        __syncthreads();
        for (int fc = 0; fc < 2; fc++) {
            load_b(w_fin + (size_t)K0 * EOUT + fc * 64, EOUT, bs, tid);
            __syncthreads();
            gemm_tile(rs, S_RS, bs, tx, ty, oacc2[fc]);
            __syncthreads();
        }
    }
    // residual: edge @ Wf[0:128]
    for (int kc3 = 0; kc3 < 2; kc3++) {
        for (int fc = 0; fc < 2; fc++) {
            load_b(w_fin + (size_t)(kc3 * 64) * EOUT + fc * 64, EOUT, bs, tid);
            __syncthreads();
            gemm_tile(es + kc3 * 64, S_ES, bs, tx, ty, oacc2[fc]);
            __syncthreads();
        }
    }

    // ---- epilogue: + Pfi + Pfj, write o into es buffer ----
#pragma unroll
    for (int fc = 0; fc < 2; fc++) {
        const int n = fc * 64 + tx * 4;
        const float4 pfi = *(const float4*)(g_pfi + (size_t)i * EOUT + n);
#pragma unroll
        for (int r = 0; r < 4; r++) {
            int m = ty * 4 + r;
            float4 pfj = *(const float4*)(g_pfj + (size_t)(j0 + m) * EOUT + n);
            float v0, v1, v2, v3;
            upk(oacc2[fc][r][0], v0, v1); upk(oacc2[fc][r][1], v2, v3);
            float* d = es + m * S_ES + n;
            d[0] = v0 + pfi.x + pfj.x;
            d[1] = v1 + pfi.y + pfj.y;
            d[2] = v2 + pfi.z + pfj.z;
            d[3] = v3 + pfi.w + pfj.w;
        }
    }
    __syncthreads();

    // ---- LayerNorm over 128 + write out ----
    const int lane = tid & 31, wp = tid >> 5;
    const float g0 = ln_g[lane],      b0 = ln_b[lane];
    const float g1 = ln_g[lane + 32], b1 = ln_b[lane + 32];
    const float g2 = ln_g[lane + 64], b2 = ln_b[lane + 64];
    const float g3 = ln_g[lane + 96], b3 = ln_b[lane + 96];
#pragma unroll
    for (int rr = 0; rr < 8; rr++) {
        int m = wp * 8 + rr;
        const float* row = es + m * S_ES;
        float v0 = row[lane], v1 = row[lane + 32], v2 = row[lane + 64], v3 = row[lane + 96];
        float s = v0 + v1 + v2 + v3;
#pragma unroll
        for (int off = 16; off; off >>= 1) s += __shfl_xor_sync(0xffffffffu, s, off);
        float mu = s * (1.0f / 128.0f);
        float d0 = v0 - mu, d1 = v1 - mu, d2 = v2 - mu, d3 = v3 - mu;
        float q = d0 * d0 + d1 * d1 + d2 * d2 + d3 * d3;
#pragma unroll
        for (int off = 16; off; off >>= 1) q += __shfl_xor_sync(0xffffffffu, q, off);
        float rstd = rsqrtf(q * (1.0f / 128.0f) + 1e-5f);
        float* op = out + (size_t)(i * NSEQ + j0 + m) * EOUT;
        op[lane]      = d0 * rstd * g0 + b0;
        op[lane + 32] = d1 * rstd * g1 + b1;
        op[lane + 64] = d2 * rstd * g2 + b2;
        op[lane + 96] = d3 * rstd * g3 + b3;
    }
}

// ---------------------------------------------------------------------------
extern "C" void kernel_launch(void* const* d_in, const int* in_sizes, int n_in,
                              void* d_out, int out_size) {
    const float* node   = (const float*)d_in[0];
    const float* edge   = (const float*)d_in[1];
    const float* w_init = (const float*)d_in[2];
    const float* b_init = (const float*)d_in[3];
    const float* w_t0   = (const float*)d_in[4];
    const float* b_t0   = (const float*)d_in[5];
    const float* w_t1   = (const float*)d_in[6];
    const float* b_t1   = (const float*)d_in[7];
    const float* w_fin  = (const float*)d_in[8];
    const float* b_fin  = (const float*)d_in[9];
    const float* ln_g   = (const float*)d_in[10];
    const float* ln_b   = (const float*)d_in[11];
    float* out = (float*)d_out;

    (void)in_sizes; (void)n_in; (void)out_size;

    const int smem_bytes = SMEM_FLOATS * sizeof(float);   // 166,912 B
    cudaFuncSetAttribute(fused_kernel,
                         cudaFuncAttributeMaxDynamicSharedMemorySize, smem_bytes);

    nb_kernel<<<NSEQ, 128>>>(node, w_init, b_init);
    pre_kernel<<<NSEQ, HID>>>(w_t0, b_t0, w_fin, b_fin);
    fused_kernel<<<4096, 256, smem_bytes>>>(edge, w_t0, w_t1, b_t1, w_fin,
                                            ln_g, ln_b, out);
}

// round 4
// speedup vs baseline: 1.0011x; 1.0011x over previous
#include <cuda_runtime.h>
#include <cstddef>

// ---------------------------------------------------------------------------
// EdgeTransition, algebraically reduced + fully fused.
//   nb   = node @ w_init + b_init                       [512,128]
//   P0i  = nb @ W0[128:256] + b0     P0j = nb @ W0[256:384]      [512,384]
//   Pfi  = nb @ Wf[128:256] + bf     Pfj = nb @ Wf[256:384]      [512,128]
//   per edge tile (64 rows, same i):
//     t0 = relu(edge @ W0[0:128] + P0i[i] + P0j[j])
//     t1 = relu(t0 @ W1 + b1)             (chunked, never materialized fully)
//     o  = t1 @ Wf + edge @ Wf[0:128] + Pfi[i] + Pfj[j]
//     out = LayerNorm(o) * g + b
// ---------------------------------------------------------------------------

#define NSEQ   512
#define BIASD  128
#define HID    384
#define EOUT   128
#define TM     64

// strides (floats) with +4 pad to break bank conflicts on A reads
#define S_ES   132
#define S_T0   388
#define S_RS   68

__device__ float g_nb [NSEQ * BIASD];
__device__ float g_p0i[NSEQ * HID];
__device__ float g_p0j[NSEQ * HID];
__device__ float g_pfi[NSEQ * EOUT];
__device__ float g_pfj[NSEQ * EOUT];

typedef unsigned long long u64;

__device__ __forceinline__ u64 pk(float x, float y) {
    u64 r; asm("mov.b64 %0, {%1, %2};" : "=l"(r) : "f"(x), "f"(y)); return r;
}
__device__ __forceinline__ void upk(u64 r, float& x, float& y) {
    asm("mov.b64 {%0, %1}, %2;" : "=f"(x), "=f"(y) : "l"(r));
}
__device__ __forceinline__ void fma2(u64& d, u64 a, u64 b) {
    asm("fma.rn.f32x2 %0, %1, %2, %0;" : "+l"(d) : "l"(a), "l"(b));
}

// ---------------------------------------------------------------------------
// nb = node_embed @ w_init + b_init
__global__ void nb_kernel(const float* __restrict__ node,
                          const float* __restrict__ w_init,
                          const float* __restrict__ b_init) {
    __shared__ float xs[256];
    int i = blockIdx.x, t = threadIdx.x;   // 128 threads
    xs[t]       = node[i * 256 + t];
    xs[t + 128] = node[i * 256 + 128 + t];
    __syncthreads();
    float acc = b_init[t];
#pragma unroll 8
    for (int k = 0; k < 256; k++) acc += xs[k] * w_init[k * 128 + t];
    g_nb[i * 128 + t] = acc;
}

// ---------------------------------------------------------------------------
// per-row bias tables
__global__ void pre_kernel(const float* __restrict__ w_t0,
                           const float* __restrict__ b_t0,
                           const float* __restrict__ w_fin,
                           const float* __restrict__ b_fin) {
    __shared__ float nbs[128];
    int i = blockIdx.x, t = threadIdx.x;   // 384 threads
    if (t < 128) nbs[t] = g_nb[i * 128 + t];
    __syncthreads();
    float a0 = b_t0[t], a1 = 0.f;
#pragma unroll 8
    for (int k = 0; k < 128; k++) {
        float v = nbs[k];
        a0 += v * w_t0[(128 + k) * HID + t];
        a1 += v * w_t0[(256 + k) * HID + t];
    }
    g_p0i[i * HID + t] = a0;
    g_p0j[i * HID + t] = a1;
    if (t < 128) {
        float f0 = b_fin[t], f1 = 0.f;
#pragma unroll 8
        for (int k = 0; k < 128; k++) {
            float v = nbs[k];
            f0 += v * w_fin[(128 + k) * EOUT + t];
            f1 += v * w_fin[(256 + k) * EOUT + t];
        }
        g_pfi[i * EOUT + t] = f0;
        g_pfj[i * EOUT + t] = f1;
    }
}

// ---------------------------------------------------------------------------
// 64x64 B tile loader: bs[k][n] = g[k*ldg + n]
__device__ __forceinline__ void load_b(const float* __restrict__ g, int ldg,
                                       float* __restrict__ bs, int tid) {
#pragma unroll
    for (int v = tid; v < 1024; v += 256) {
        int k = v >> 4, c = (v & 15) * 4;
        *(float4*)(bs + k * 64 + c) = *(const float4*)(g + (size_t)k * ldg + c);
    }
}

// 64x64x64 micro-GEMM, 4x4 per thread, packed f32x2 FMAs along n
__device__ __forceinline__ void gemm_tile(const float* __restrict__ A, int lda,
                                          const float* __restrict__ bs,
                                          int tx, int ty, u64 acc2[4][2]) {
    const float* a0p = A + (ty * 4 + 0) * lda;
    const float* a1p = A + (ty * 4 + 1) * lda;
    const float* a2p = A + (ty * 4 + 2) * lda;
    const float* a3p = A + (ty * 4 + 3) * lda;
    const float* bp0 = bs + tx * 4;
#pragma unroll 8
    for (int k = 0; k < 64; k++) {
        u64 b01 = *(const u64*)(bp0 + k * 64);
        u64 b23 = *(const u64*)(bp0 + k * 64 + 2);
        u64 aa0 = pk(a0p[k], a0p[k]);
        u64 aa1 = pk(a1p[k], a1p[k]);
        u64 aa2 = pk(a2p[k], a2p[k]);
        u64 aa3 = pk(a3p[k], a3p[k]);
        fma2(acc2[0][0], aa0, b01); fma2(acc2[0][1], aa0, b23);
        fma2(acc2[1][0], aa1, b01); fma2(acc2[1][1], aa1, b23);
        fma2(acc2[2][0], aa2, b01); fma2(acc2[2][1], aa2, b23);
        fma2(acc2[3][0], aa3, b01); fma2(acc2[3][1], aa3, b23);
    }
}

#define SMEM_FLOATS (TM * S_ES + TM * S_T0 + 64 * 64 + TM * S_RS)

__global__ void __launch_bounds__(256, 1)
fused_kernel(const float* __restrict__ edge,
             const float* __restrict__ w_t0,
             const float* __restrict__ w_t1,
             const float* __restrict__ b_t1,
             const float* __restrict__ w_fin,
             const float* __restrict__ ln_g,
             const float* __restrict__ ln_b,
             float* __restrict__ out) {
    extern __shared__ float sm[];
    float* es  = sm;                       // [64][132] edge tile, later o tile
    float* t0s = sm + TM * S_ES;           // [64][388]
    float* bs  = t0s + TM * S_T0;          // [64][64]
    float* rs  = bs + 64 * 64;             // [64][68]

    const int tile = blockIdx.x;           // 4096 tiles
    const int i    = tile >> 3;
    const int j0   = (tile & 7) << 6;
    const int tid  = threadIdx.x;
    const int tx   = tid & 15, ty = tid >> 4;

    // ---- load edge tile [64,128] ----
    {
        const float4* src = (const float4*)(edge + (size_t)(i * NSEQ + j0) * 128);
#pragma unroll
        for (int v = tid; v < 2048; v += 256) {
            int r = v >> 5, c = v & 31;
            *(float4*)(es + r * S_ES + c * 4) = src[r * 32 + c];
        }
    }
    __syncthreads();

    // ---- layer 0: t0 = relu(edge @ W0_top + P0i + P0j) ----
    for (int nc = 0; nc < 6; nc++) {
        const int n0 = nc * 64;
        u64 acc2[4][2] = {};
        for (int kc = 0; kc < 2; kc++) {
            load_b(w_t0 + (size_t)(kc * 64) * HID + n0, HID, bs, tid);
            __syncthreads();
            gemm_tile(es + kc * 64, S_ES, bs, tx, ty, acc2);
            __syncthreads();
        }
        const float4 pi = *(const float4*)(g_p0i + (size_t)i * HID + n0 + tx * 4);
#pragma unroll
        for (int r = 0; r < 4; r++) {
            int m = ty * 4 + r;
            float4 pj = *(const float4*)(g_p0j + (size_t)(j0 + m) * HID + n0 + tx * 4);
            float v0, v1, v2, v3;
            upk(acc2[r][0], v0, v1); upk(acc2[r][1], v2, v3);
            float* d = t0s + m * S_T0 + n0 + tx * 4;
            d[0] = fmaxf(v0 + pi.x + pj.x, 0.f);
            d[1] = fmaxf(v1 + pi.y + pj.y, 0.f);
            d[2] = fmaxf(v2 + pi.z + pj.z, 0.f);
            d[3] = fmaxf(v3 + pi.w + pj.w, 0.f);
        }
    }
    __syncthreads();

    // ---- layer 1 + final GEMM, t1 chunked (never materialized) ----
    u64 oacc2[2][4][2] = {};
    for (int kc2 = 0; kc2 < 6; kc2++) {
        const int K0 = kc2 * 64;
        u64 acc2[4][2] = {};
        for (int kc = 0; kc < 6; kc++) {
            load_b(w_t1 + (size_t)(kc * 64) * HID + K0, HID, bs, tid);
            __syncthreads();
            gemm_tile(t0s + kc * 64, S_T0, bs, tx, ty, acc2);
            __syncthreads();
        }
        {   // relu + b1 -> rs chunk [64,64]
            const float4 bb = *(const float4*)(b_t1 + K0 + tx * 4);
#pragma unroll
            for (int r = 0; r < 4; r++) {
                float v0, v1, v2, v3;
                upk(acc2[r][0], v0, v1); upk(acc2[r][1], v2, v3);
                float* d = rs + (ty * 4 + r) * S_RS + tx * 4;
                d[0] = fmaxf(v0 + bb.x, 0.f);
                d[1] = fmaxf(v1 + bb.y, 0.f);
                d[2] = fmaxf(v2 + bb.z, 0.f);
                d[3] = fmaxf(v3 + bb.w, 0.f);
            }
        }
        __syncthreads();
        for (int fc = 0; fc < 2; fc++) {
            load_b(w_fin + (size_t)K0 * EOUT + fc * 64, EOUT, bs, tid);
            __syncthreads();
            gemm_tile(rs, S_RS, bs, tx, ty, oacc2[fc]);
            __syncthreads();
        }
    }
    // residual: edge @ Wf[0:128]
    for (int kc3 = 0; kc3 < 2; kc3++) {
        for (int fc = 0; fc < 2; fc++) {
            load_b(w_fin + (size_t)(kc3 * 64) * EOUT + fc * 64, EOUT, bs, tid);
            __syncthreads();
            gemm_tile(es + kc3 * 64, S_ES, bs, tx, ty, oacc2[fc]);
            __syncthreads();
        }
    }

    // ---- epilogue: + Pfi + Pfj, write o into es buffer ----
#pragma unroll
    for (int fc = 0; fc < 2; fc++) {
        const int n = fc * 64 + tx * 4;
        const float4 pfi = *(const float4*)(g_pfi + (size_t)i * EOUT + n);
#pragma unroll
        for (int r = 0; r < 4; r++) {
            int m = ty * 4 + r;
            float4 pfj = *(const float4*)(g_pfj + (size_t)(j0 + m) * EOUT + n);
            float v0, v1, v2, v3;
            upk(oacc2[fc][r][0], v0, v1); upk(oacc2[fc][r][1], v2, v3);
            float* d = es + m * S_ES + n;
            d[0] = v0 + pfi.x + pfj.x;
            d[1] = v1 + pfi.y + pfj.y;
            d[2] = v2 + pfi.z + pfj.z;
            d[3] = v3 + pfi.w + pfj.w;
        }
    }
    __syncthreads();

    // ---- LayerNorm over 128 + write out ----
    const int lane = tid & 31, wp = tid >> 5;
    const float g0 = ln_g[lane],      b0 = ln_b[lane];
    const float g1 = ln_g[lane + 32], b1 = ln_b[lane + 32];
    const float g2 = ln_g[lane + 64], b2 = ln_b[lane + 64];
    const float g3 = ln_g[lane + 96], b3 = ln_b[lane + 96];
#pragma unroll
    for (int rr = 0; rr < 8; rr++) {
        int m = wp * 8 + rr;
        const float* row = es + m * S_ES;
        float v0 = row[lane], v1 = row[lane + 32], v2 = row[lane + 64], v3 = row[lane + 96];
        float s = v0 + v1 + v2 + v3;
#pragma unroll
        for (int off = 16; off; off >>= 1) s += __shfl_xor_sync(0xffffffffu, s, off);
        float mu = s * (1.0f / 128.0f);
        float d0 = v0 - mu, d1 = v1 - mu, d2 = v2 - mu, d3 = v3 - mu;
        float q = d0 * d0 + d1 * d1 + d2 * d2 + d3 * d3;
#pragma unroll
        for (int off = 16; off; off >>= 1) q += __shfl_xor_sync(0xffffffffu, q, off);
        float rstd = rsqrtf(q * (1.0f / 128.0f) + 1e-5f);
        float* op = out + (size_t)(i * NSEQ + j0 + m) * EOUT;
        op[lane]      = d0 * rstd * g0 + b0;
        op[lane + 32] = d1 * rstd * g1 + b1;
        op[lane + 64] = d2 * rstd * g2 + b2;
        op[lane + 96] = d3 * rstd * g3 + b3;
    }
}

// ---------------------------------------------------------------------------
extern "C" void kernel_launch(void* const* d_in, const int* in_sizes, int n_in,
                              void* d_out, int out_size) {
    const float* node   = (const float*)d_in[0];
    const float* edge   = (const float*)d_in[1];
    const float* w_init = (const float*)d_in[2];
    const float* b_init = (const float*)d_in[3];
    const float* w_t0   = (const float*)d_in[4];
    const float* b_t0   = (const float*)d_in[5];
    const float* w_t1   = (const float*)d_in[6];
    const float* b_t1   = (const float*)d_in[7];
    const float* w_fin  = (const float*)d_in[8];
    const float* b_fin  = (const float*)d_in[9];
    const float* ln_g   = (const float*)d_in[10];
    const float* ln_b   = (const float*)d_in[11];
    float* out = (float*)d_out;

    (void)in_sizes; (void)n_in; (void)out_size;

    const int smem_bytes = SMEM_FLOATS * sizeof(float);   // 166,912 B
    cudaFuncSetAttribute(fused_kernel,
                         cudaFuncAttributeMaxDynamicSharedMemorySize, smem_bytes);

    nb_kernel<<<NSEQ, 128>>>(node, w_init, b_init);
    pre_kernel<<<NSEQ, HID>>>(w_t0, b_t0, w_fin, b_fin);
    fused_kernel<<<4096, 256, smem_bytes>>>(edge, w_t0, w_t1, b_t1, w_fin,
                                            ln_g, ln_b, out);
}

// round 5
// speedup vs baseline: 1.0022x; 1.0011x over previous
#include <cuda_runtime.h>
#include <cstddef>

// ---------------------------------------------------------------------------
// EdgeTransition, algebraically reduced + fully fused.
//   nb   = node @ w_init + b_init                       [512,128]
//   P0i  = nb @ W0[128:256] + b0     P0j = nb @ W0[256:384]      [512,384]
//   Pfi  = nb @ Wf[128:256] + bf     Pfj = nb @ Wf[256:384]      [512,128]
//   per edge tile (64 rows, same i):
//     t0 = relu(edge @ W0[0:128] + P0i[i] + P0j[j])
//     t1 = relu(t0 @ W1 + b1)             (chunked, never materialized fully)
//     o  = t1 @ Wf + edge @ Wf[0:128] + Pfi[i] + Pfj[j]
//     out = LayerNorm(o) * g + b
// ---------------------------------------------------------------------------

#define NSEQ   512
#define BIASD  128
#define HID    384
#define EOUT   128
#define TM     64

// strides (floats) with +4 pad to break bank conflicts on A reads
#define S_ES   132
#define S_T0   388
#define S_RS   68

__device__ float g_nb [NSEQ * BIASD];
__device__ float g_p0i[NSEQ * HID];
__device__ float g_p0j[NSEQ * HID];
__device__ float g_pfi[NSEQ * EOUT];
__device__ float g_pfj[NSEQ * EOUT];

typedef unsigned long long u64;

__device__ __forceinline__ u64 pk(float x, float y) {
    u64 r; asm("mov.b64 %0, {%1, %2};" : "=l"(r) : "f"(x), "f"(y)); return r;
}
__device__ __forceinline__ void upk(u64 r, float& x, float& y) {
    asm("mov.b64 {%0, %1}, %2;" : "=f"(x), "=f"(y) : "l"(r));
}
__device__ __forceinline__ void fma2(u64& d, u64 a, u64 b) {
    asm("fma.rn.f32x2 %0, %1, %2, %0;" : "+l"(d) : "l"(a), "l"(b));
}

// ---------------------------------------------------------------------------
// nb = node_embed @ w_init + b_init
__global__ void nb_kernel(const float* __restrict__ node,
                          const float* __restrict__ w_init,
                          const float* __restrict__ b_init) {
    __shared__ float xs[256];
    int i = blockIdx.x, t = threadIdx.x;   // 128 threads
    xs[t]       = node[i * 256 + t];
    xs[t + 128] = node[i * 256 + 128 + t];
    __syncthreads();
    float acc = b_init[t];
#pragma unroll 8
    for (int k = 0; k < 256; k++) acc += xs[k] * w_init[k * 128 + t];
    g_nb[i * 128 + t] = acc;
}

// ---------------------------------------------------------------------------
// per-row bias tables
__global__ void pre_kernel(const float* __restrict__ w_t0,
                           const float* __restrict__ b_t0,
                           const float* __restrict__ w_fin,
                           const float* __restrict__ b_fin) {
    __shared__ float nbs[128];
    int i = blockIdx.x, t = threadIdx.x;   // 384 threads
    if (t < 128) nbs[t] = g_nb[i * 128 + t];
    __syncthreads();
    float a0 = b_t0[t], a1 = 0.f;
#pragma unroll 8
    for (int k = 0; k < 128; k++) {
        float v = nbs[k];
        a0 += v * w_t0[(128 + k) * HID + t];
        a1 += v * w_t0[(256 + k) * HID + t];
    }
    g_p0i[i * HID + t] = a0;
    g_p0j[i * HID + t] = a1;
    if (t < 128) {
        float f0 = b_fin[t], f1 = 0.f;
#pragma unroll 8
        for (int k = 0; k < 128; k++) {
            float v = nbs[k];
            f0 += v * w_fin[(128 + k) * EOUT + t];
            f1 += v * w_fin[(256 + k) * EOUT + t];
        }
        g_pfi[i * EOUT + t] = f0;
        g_pfj[i * EOUT + t] = f1;
    }
}

// ---------------------------------------------------------------------------
// 64x64 B tile loader: bs[k][n] = g[k*ldg + n]
__device__ __forceinline__ void load_b(const float* __restrict__ g, int ldg,
                                       float* __restrict__ bs, int tid) {
#pragma unroll
    for (int v = tid; v < 1024; v += 256) {
        int k = v >> 4, c = (v & 15) * 4;
        *(float4*)(bs + k * 64 + c) = *(const float4*)(g + (size_t)k * ldg + c);
    }
}

// 64x64x64 micro-GEMM, 4x4 per thread, packed f32x2 FMAs along n
__device__ __forceinline__ void gemm_tile(const float* __restrict__ A, int lda,
                                          const float* __restrict__ bs,
                                          int tx, int ty, u64 acc2[4][2]) {
    const float* a0p = A + (ty * 4 + 0) * lda;
    const float* a1p = A + (ty * 4 + 1) * lda;
    const float* a2p = A + (ty * 4 + 2) * lda;
    const float* a3p = A + (ty * 4 + 3) * lda;
    const float* bp0 = bs + tx * 4;
#pragma unroll 8
    for (int k = 0; k < 64; k++) {
        u64 b01 = *(const u64*)(bp0 + k * 64);
        u64 b23 = *(const u64*)(bp0 + k * 64 + 2);
        u64 aa0 = pk(a0p[k], a0p[k]);
        u64 aa1 = pk(a1p[k], a1p[k]);
        u64 aa2 = pk(a2p[k], a2p[k]);
        u64 aa3 = pk(a3p[k], a3p[k]);
        fma2(acc2[0][0], aa0, b01); fma2(acc2[0][1], aa0, b23);
        fma2(acc2[1][0], aa1, b01); fma2(acc2[1][1], aa1, b23);
        fma2(acc2[2][0], aa2, b01); fma2(acc2[2][1], aa2, b23);
        fma2(acc2[3][0], aa3, b01); fma2(acc2[3][1], aa3, b23);
    }
}

#define SMEM_FLOATS (TM * S_ES + TM * S_T0 + 64 * 64 + TM * S_RS)

__global__ void __launch_bounds__(256, 1)
fused_kernel(const float* __restrict__ edge,
             const float* __restrict__ w_t0,
             const float* __restrict__ w_t1,
             const float* __restrict__ b_t1,
             const float* __restrict__ w_fin,
             const float* __restrict__ ln_g,
             const float* __restrict__ ln_b,
             float* __restrict__ out) {
    extern __shared__ float sm[];
    float* es  = sm;                       // [64][132] edge tile, later o tile
    float* t0s = sm + TM * S_ES;           // [64][388]
    float* bs  = t0s + TM * S_T0;          // [64][64]
    float* rs  = bs + 64 * 64;             // [64][68]

    const int tile = blockIdx.x;           // 4096 tiles
    const int i    = tile >> 3;
    const int j0   = (tile & 7) << 6;
    const int tid  = threadIdx.x;
    const int tx   = tid & 15, ty = tid >> 4;

    // ---- load edge tile [64,128] ----
    {
        const float4* src = (const float4*)(edge + (size_t)(i * NSEQ + j0) * 128);
#pragma unroll
        for (int v = tid; v < 2048; v += 256) {
            int r = v >> 5, c = v & 31;
            *(float4*)(es + r * S_ES + c * 4) = src[r * 32 + c];
        }
    }
    __syncthreads();

    // ---- layer 0: t0 = relu(edge @ W0_top + P0i + P0j) ----
    for (int nc = 0; nc < 6; nc++) {
        const int n0 = nc * 64;
        u64 acc2[4][2] = {};
        for (int kc = 0; kc < 2; kc++) {
            load_b(w_t0 + (size_t)(kc * 64) * HID + n0, HID, bs, tid);
            __syncthreads();
            gemm_tile(es + kc * 64, S_ES, bs, tx, ty, acc2);
            __syncthreads();
        }
        const float4 pi = *(const float4*)(g_p0i + (size_t)i * HID + n0 + tx * 4);
#pragma unroll
        for (int r = 0; r < 4; r++) {
            int m = ty * 4 + r;
            float4 pj = *(const float4*)(g_p0j + (size_t)(j0 + m) * HID + n0 + tx * 4);
            float v0, v1, v2, v3;
            upk(acc2[r][0], v0, v1); upk(acc2[r][1], v2, v3);
            float* d = t0s + m * S_T0 + n0 + tx * 4;
            d[0] = fmaxf(v0 + pi.x + pj.x, 0.f);
            d[1] = fmaxf(v1 + pi.y + pj.y, 0.f);
            d[2] = fmaxf(v2 + pi.z + pj.z, 0.f);
            d[3] = fmaxf(v3 + pi.w + pj.w, 0.f);
        }
    }
    __syncthreads();

    // ---- layer 1 + final GEMM, t1 chunked (never materialized) ----
    u64 oacc2[2][4][2] = {};
    for (int kc2 = 0; kc2 < 6; kc2++) {
        const int K0 = kc2 * 64;
        u64 acc2[4][2] = {};
        for (int kc = 0; kc < 6; kc++) {
            load_b(w_t1 + (size_t)(kc * 64) * HID + K0, HID, bs, tid);
            __syncthreads();
            gemm_tile(t0s + kc * 64, S_T0, bs, tx, ty, acc2);
            __syncthreads();
        }
        {   // relu + b1 -> rs chunk [64,64]
            const float4 bb = *(const float4*)(b_t1 + K0 + tx * 4);
#pragma unroll
            for (int r = 0; r < 4; r++) {
                float v0, v1, v2, v3;
                upk(acc2[r][0], v0, v1); upk(acc2[r][1], v2, v3);
                float* d = rs + (ty * 4 + r) * S_RS + tx * 4;
                d[0] = fmaxf(v0 + bb.x, 0.f);
                d[1] = fmaxf(v1 + bb.y, 0.f);
                d[2] = fmaxf(v2 + bb.z, 0.f);
                d[3] = fmaxf(v3 + bb.w, 0.f);
            }
        }
        __syncthreads();
        for (int fc = 0; fc < 2; fc++) {
            load_b(w_fin + (size_t)K0 * EOUT + fc * 64, EOUT, bs, tid);
            __syncthreads();
            gemm_tile(rs, S_RS, bs, tx, ty, oacc2[fc]);
            __syncthreads();
        }
    }
    // residual: edge @ Wf[0:128]
    for (int kc3 = 0; kc3 < 2; kc3++) {
        for (int fc = 0; fc < 2; fc++) {
            load_b(w_fin + (size_t)(kc3 * 64) * EOUT + fc * 64, EOUT, bs, tid);
            __syncthreads();
            gemm_tile(es + kc3 * 64, S_ES, bs, tx, ty, oacc2[fc]);
            __syncthreads();
        }
    }

    // ---- epilogue: + Pfi + Pfj, write o into es buffer ----
#pragma unroll
    for (int fc = 0; fc < 2; fc++) {
        const int n = fc * 64 + tx * 4;
        const float4 pfi = *(const float4*)(g_pfi + (size_t)i * EOUT + n);
#pragma unroll
        for (int r = 0; r < 4; r++) {
            int m = ty * 4 + r;
            float4 pfj = *(const float4*)(g_pfj + (size_t)(j0 + m) * EOUT + n);
            float v0, v1, v2, v3;
            upk(oacc2[fc][r][0], v0, v1); upk(oacc2[fc][r][1], v2, v3);
            float* d = es + m * S_ES + n;
            d[0] = v0 + pfi.x + pfj.x;
            d[1] = v1 + pfi.y + pfj.y;
            d[2] = v2 + pfi.z + pfj.z;
            d[3] = v3 + pfi.w + pfj.w;
        }
    }
    __syncthreads();

    // ---- LayerNorm over 128 + write out ----
    const int lane = tid & 31, wp = tid >> 5;
    const float g0 = ln_g[lane],      b0 = ln_b[lane];
    const float g1 = ln_g[lane + 32], b1 = ln_b[lane + 32];
    const float g2 = ln_g[lane + 64], b2 = ln_b[lane + 64];
    const float g3 = ln_g[lane + 96], b3 = ln_b[lane + 96];
#pragma unroll
    for (int rr = 0; rr < 8; rr++) {
        int m = wp * 8 + rr;
        const float* row = es + m * S_ES;
        float v0 = row[lane], v1 = row[lane + 32], v2 = row[lane + 64], v3 = row[lane + 96];
        float s = v0 + v1 + v2 + v3;
#pragma unroll
        for (int off = 16; off; off >>= 1) s += __shfl_xor_sync(0xffffffffu, s, off);
        float mu = s * (1.0f / 128.0f);
        float d0 = v0 - mu, d1 = v1 - mu, d2 = v2 - mu, d3 = v3 - mu;
        float q = d0 * d0 + d1 * d1 + d2 * d2 + d3 * d3;
#pragma unroll
        for (int off = 16; off; off >>= 1) q += __shfl_xor_sync(0xffffffffu, q, off);
        float rstd = rsqrtf(q * (1.0f / 128.0f) + 1e-5f);
        float* op = out + (size_t)(i * NSEQ + j0 + m) * EOUT;
        op[lane]      = d0 * rstd * g0 + b0;
        op[lane + 32] = d1 * rstd * g1 + b1;
        op[lane + 64] = d2 * rstd * g2 + b2;
        op[lane + 96] = d3 * rstd * g3 + b3;
    }
}

// ---------------------------------------------------------------------------
extern "C" void kernel_launch(void* const* d_in, const int* in_sizes, int n_in,
                              void* d_out, int out_size) {
    const float* node   = (const float*)d_in[0];
    const float* edge   = (const float*)d_in[1];
    const float* w_init = (const float*)d_in[2];
    const float* b_init = (const float*)d_in[3];
    const float* w_t0   = (const float*)d_in[4];
    const float* b_t0   = (const float*)d_in[5];
    const float* w_t1   = (const float*)d_in[6];
    const float* b_t1   = (const float*)d_in[7];
    const float* w_fin  = (const float*)d_in[8];
    const float* b_fin  = (const float*)d_in[9];
    const float* ln_g   = (const float*)d_in[10];
    const float* ln_b   = (const float*)d_in[11];
    float* out = (float*)d_out;

    (void)in_sizes; (void)n_in; (void)out_size;

    const int smem_bytes = SMEM_FLOATS * sizeof(float);   // 166,912 B
    cudaFuncSetAttribute(fused_kernel,
                         cudaFuncAttributeMaxDynamicSharedMemorySize, smem_bytes);

    nb_kernel<<<NSEQ, 128>>>(node, w_init, b_init);
    pre_kernel<<<NSEQ, HID>>>(w_t0, b_t0, w_fin, b_fin);
    fused_kernel<<<4096, 256, smem_bytes>>>(edge, w_t0, w_t1, b_t1, w_fin,
                                            ln_g, ln_b, out);
}

// round 9
// speedup vs baseline: 4.8675x; 4.8569x over previous
#include <cuda_runtime.h>
#include <cuda_fp16.h>
#include <cstdint>
#include <cstddef>

#define NSEQ 512
#define HID  384
#define EOUT 128

// ---------------------------------------------------------------------------
// device-global scratch (no allocations allowed)
// ---------------------------------------------------------------------------
__device__ float g_nb [NSEQ * 128];
__device__ __align__(16) float g_p0i[NSEQ * HID];
__device__ __align__(16) float g_p0j[NSEQ * HID];
__device__ __align__(16) float g_pfi[NSEQ * EOUT];
__device__ __align__(16) float g_pfj[NSEQ * EOUT];
// transposed fp16 weights, [N][K] row-major
__device__ __align__(16) __half g_w0h[HID  * 128];   // W0top^T  [384][128]
__device__ __align__(16) __half g_wrh[EOUT * 128];   // Wf_top^T [128][128]
__device__ __align__(16) __half g_w1h[HID  * HID];   // W1^T     [384][384]
__device__ __align__(16) __half g_wfh[EOUT * HID];   // Wf^T     [128][384]

// ---------------------------------------------------------------------------
// helpers (baseline PTX only: mma.sync / ldmatrix / cp.async — no 'a' features)
// ---------------------------------------------------------------------------
__device__ __forceinline__ uint32_t smem_u32(const void* p) {
    uint32_t a;
    asm("{ .reg .u64 t; cvta.to.shared.u64 t, %1; cvt.u32.u64 %0, t; }"
        : "=r"(a) : "l"(p));
    return a;
}
__device__ __forceinline__ void cpa16(uint32_t dst, const void* src) {
    asm volatile("cp.async.cg.shared.global [%0], [%1], 16;"
                 :: "r"(dst), "l"(src));
}
#define CP_COMMIT() asm volatile("cp.async.commit_group;" ::: "memory")
#define CP_WAIT(n)  asm volatile("cp.async.wait_group %0;" :: "n"(n) : "memory")

__device__ __forceinline__ void ldmx4(uint32_t* r, uint32_t a) {
    asm volatile("ldmatrix.sync.aligned.m8n8.x4.shared.b16 {%0,%1,%2,%3}, [%4];"
                 : "=r"(r[0]), "=r"(r[1]), "=r"(r[2]), "=r"(r[3]) : "r"(a));
}
__device__ __forceinline__ void mma16(float* c, const uint32_t* a, const uint32_t* b) {
    asm volatile("mma.sync.aligned.m16n8k16.row.col.f32.f16.f16.f32 "
                 "{%0,%1,%2,%3},{%4,%5,%6,%7},{%8,%9},{%0,%1,%2,%3};"
                 : "+f"(c[0]), "+f"(c[1]), "+f"(c[2]), "+f"(c[3])
                 : "r"(a[0]), "r"(a[1]), "r"(a[2]), "r"(a[3]),
                   "r"(b[0]), "r"(b[1]));
}

// ---------------------------------------------------------------------------
// prep kernels
// ---------------------------------------------------------------------------
__global__ void nb_kernel(const float* __restrict__ node,
                          const float* __restrict__ w_init,
                          const float* __restrict__ b_init) {
    __shared__ float xs[256];
    int i = blockIdx.x, t = threadIdx.x;   // 128 threads
    xs[t]       = node[i * 256 + t];
    xs[t + 128] = node[i * 256 + 128 + t];
    __syncthreads();
    float acc = b_init[t];
#pragma unroll 8
    for (int k = 0; k < 256; k++) acc += xs[k] * w_init[k * 128 + t];
    g_nb[i * 128 + t] = acc;
}

__global__ void pre_kernel(const float* __restrict__ w_t0,
                           const float* __restrict__ b_t0,
                           const float* __restrict__ w_fin,
                           const float* __restrict__ b_fin) {
    __shared__ float nbs[128];
    int i = blockIdx.x, t = threadIdx.x;   // 384 threads
    if (t < 128) nbs[t] = g_nb[i * 128 + t];
    __syncthreads();
    float a0 = b_t0[t], a1 = 0.f;
#pragma unroll 8
    for (int k = 0; k < 128; k++) {
        float v = nbs[k];
        a0 += v * w_t0[(128 + k) * HID + t];
        a1 += v * w_t0[(256 + k) * HID + t];
    }
    g_p0i[i * HID + t] = a0;
    g_p0j[i * HID + t] = a1;
    if (t < 128) {
        float f0 = b_fin[t], f1 = 0.f;
#pragma unroll 8
        for (int k = 0; k < 128; k++) {
            float v = nbs[k];
            f0 += v * w_fin[(128 + k) * EOUT + t];
            f1 += v * w_fin[(256 + k) * EOUT + t];
        }
        g_pfi[i * EOUT + t] = f0;
        g_pfj[i * EOUT + t] = f1;
    }
}

// transpose + fp16-convert weights: dst[n][k] = (half)W[k][n]
__global__ void packh_kernel(const float* __restrict__ w_t0,
                             const float* __restrict__ w_t1,
                             const float* __restrict__ w_fin) {
    const int T0 = HID * 128, T1 = EOUT * 128, T2 = HID * HID, T3 = EOUT * HID;
    for (int x = blockIdx.x * blockDim.x + threadIdx.x; x < T0 + T1 + T2 + T3;
         x += gridDim.x * blockDim.x) {
        if (x < T0) {
            int n = x >> 7, k = x & 127;
            g_w0h[x] = __float2half(w_t0[k * HID + n]);
        } else if (x < T0 + T1) {
            int y = x - T0, n = y >> 7, k = y & 127;
            g_wrh[y] = __float2half(w_fin[k * EOUT + n]);
        } else if (x < T0 + T1 + T2) {
            int y = x - T0 - T1, n = y / HID, k = y - n * HID;
            g_w1h[y] = __float2half(w_t1[k * HID + n]);
        } else {
            int y = x - T0 - T1 - T2, n = y / HID, k = y - n * HID;
            g_wfh[y] = __float2half(w_fin[k * EOUT + n]);
        }
    }
}

// ---------------------------------------------------------------------------
// fused kernel: M=64 rows per CTA, 256 threads = 8 warps (2 rowg x 4 colg)
// SMEM (bytes):
//   t0  [64][392]h @ 0        (50176)
//   rs  [64][392]h @ 50176    (50176)
//   E   [64][136]h @ 100352   (17408)   } o_buf [64][132]f @100352 (33792)
//   R   [64][136]h @ 117760   (17408)   }   overlays E+R after both dead
//   B0  [384][56]h @ 135168   (43008)
//   B1  [384][56]h @ 178176   (43008)
// total 221184
// ---------------------------------------------------------------------------
#define T0_OFF 0
#define RS_OFF 50176
#define E_OFF  100352
#define R_OFF  117760
#define O_OFF  100352
#define B0_OFF 135168
#define B1_OFF 178176
#define SMEMSZ 221184
#define LDB    56

__device__ __forceinline__ void stage(const __half* __restrict__ g, int K,
                                      int kc, int klen8, int nrows,
                                      uint32_t dst, int tid) {
    const int tot = nrows * klen8;
    for (int v = tid; v < tot; v += 256) {
        int n = v / klen8, c = v - n * klen8;
        cpa16(dst + (uint32_t)(n * LDB + c * 8) * 2,
              g + (size_t)n * K + kc + c * 8);
    }
}

// acc layout: acc[mg*NT + ng][4], mg in {0,1} (m16 groups), ng in [0,NT)
template <int NT, int KLEN, int NCH>
__device__ __forceinline__ void run_gemm(const __half* __restrict__ gB, int K,
                                         int nrows, uint32_t aBase, int lda,
                                         int n0, uint32_t bb0, uint32_t bb1,
                                         float (*acc)[4], int tid, int lane) {
    constexpr int K8 = KLEN >> 3;
    const uint32_t aro = (lane & 7) + (((lane >> 3) & 1) << 3);  // A row off
    const uint32_t ako = (lane >> 4) << 3;                       // A k off
    const uint32_t bro = (lane & 7) + ((lane >> 4) << 3);        // B row off
    const uint32_t bko = ((lane >> 3) & 1) << 3;                 // B k off

    stage(gB, K, 0, K8, nrows, bb0, tid);
    CP_COMMIT();
#pragma unroll 1
    for (int c = 0; c < NCH; c++) {
        if (c + 1 < NCH) {
            stage(gB, K, (c + 1) * KLEN, K8, nrows, (c & 1) ? bb0 : bb1, tid);
            CP_COMMIT();
            CP_WAIT(1);
        } else {
            CP_WAIT(0);
        }
        __syncthreads();
        const uint32_t bb = (c & 1) ? bb1 : bb0;
#pragma unroll
        for (int kk = 0; kk < KLEN; kk += 16) {
            uint32_t af[2][4];
#pragma unroll
            for (int mg = 0; mg < 2; mg++)
                ldmx4(af[mg], aBase + 2u * (((mg << 4) + aro) * lda +
                                            c * KLEN + kk + ako));
#pragma unroll
            for (int np = 0; np < NT / 2; np++) {
                uint32_t bf[4];
                ldmx4(bf, bb + 2u * ((n0 + (np << 4) + bro) * LDB + kk + bko));
#pragma unroll
                for (int mg = 0; mg < 2; mg++) {
                    mma16(acc[mg * NT + 2 * np],     af[mg], bf);
                    mma16(acc[mg * NT + 2 * np + 1], af[mg], bf + 2);
                }
            }
        }
        __syncthreads();
    }
}

__global__ void __launch_bounds__(256, 1)
fusedh(const float* __restrict__ edge,
       const float* __restrict__ b_t1v,
       const float* __restrict__ ln_g,
       const float* __restrict__ ln_b,
       float* __restrict__ out) {
    extern __shared__ __align__(16) char smc[];
    const uint32_t sb = smem_u32(smc);
    const int tid = threadIdx.x, lane = tid & 31, w = tid >> 5;
    const int rowg = w & 1, colg = w >> 1;      // 2 x 4 warp grid
    const int m0 = rowg << 5;                   // warp's 32-row base
    const int bidx = blockIdx.x;
    const int i = bidx >> 3, j0 = (bidx & 7) << 6;

    // ---- edge -> E (fp16, [64][136]) ----
    {
        const float4* ep = (const float4*)(edge + (size_t)(i * NSEQ + j0) * 128);
#pragma unroll
        for (int s = 0; s < 8; s++) {
            int u = tid + (s << 8);
            int r = u >> 5, c4 = u & 31;
            float4 v = ep[(r << 5) + c4];
            union { uint2 u2; __half2 h[2]; } pk;
            pk.h[0] = __floats2half2_rn(v.x, v.y);
            pk.h[1] = __floats2half2_rn(v.z, v.w);
            *(uint2*)(smc + E_OFF + (uint32_t)((r * 136 + (c4 << 2)) << 1)) = pk.u2;
        }
    }
    __syncthreads();

    const int rbase = m0 + (lane >> 2);

    // ================= phase A-1: D0 = E @ W0top  (K=128, N=384) ============
    {
        float acc[24][4];
#pragma unroll
        for (int x = 0; x < 24; x++)
#pragma unroll
            for (int y = 0; y < 4; y++) acc[x][y] = 0.f;
        run_gemm<12, 32, 4>(g_w0h, 128, HID, sb + E_OFF + m0 * 272, 136,
                            colg * 96, sb + B0_OFF, sb + B1_OFF, acc, tid, lane);
        // epilogue: t0 = relu(D0 + P0i[i] + P0j[j0+m])
        const float* p0i = g_p0i + (size_t)i * HID;
        const float* p0j = g_p0j + (size_t)j0 * HID;
#pragma unroll
        for (int mg = 0; mg < 2; mg++) {
            const int r0 = rbase + (mg << 4);
#pragma unroll
            for (int ng = 0; ng < 12; ng++) {
                const int cb = colg * 96 + (ng << 3) + ((lane & 3) << 1);
                float2 bi  = *(const float2*)(p0i + cb);
                float2 bj0 = *(const float2*)(p0j + (size_t)r0 * HID + cb);
                float2 bj1 = *(const float2*)(p0j + (size_t)(r0 + 8) * HID + cb);
                const float* a = acc[mg * 12 + ng];
                *(__half2*)(smc + T0_OFF + (uint32_t)((r0 * 392 + cb) << 1)) =
                    __floats2half2_rn(fmaxf(a[0] + bi.x + bj0.x, 0.f),
                                      fmaxf(a[1] + bi.y + bj0.y, 0.f));
                *(__half2*)(smc + T0_OFF + (uint32_t)(((r0 + 8) * 392 + cb) << 1)) =
                    __floats2half2_rn(fmaxf(a[2] + bi.x + bj1.x, 0.f),
                                      fmaxf(a[3] + bi.y + bj1.y, 0.f));
            }
        }
    }

    // ================= phase A-2: R = E @ Wf_top  (K=128, N=128) ============
    {
        float acc[8][4];
#pragma unroll
        for (int x = 0; x < 8; x++)
#pragma unroll
            for (int y = 0; y < 4; y++) acc[x][y] = 0.f;
        run_gemm<4, 32, 4>(g_wrh, 128, EOUT, sb + E_OFF + m0 * 272, 136,
                           colg * 32, sb + B0_OFF, sb + B1_OFF, acc, tid, lane);
#pragma unroll
        for (int mg = 0; mg < 2; mg++) {
            const int r0 = rbase + (mg << 4);
#pragma unroll
            for (int ng = 0; ng < 4; ng++) {
                const int cb = colg * 32 + (ng << 3) + ((lane & 3) << 1);
                const float* a = acc[mg * 4 + ng];
                *(__half2*)(smc + R_OFF + (uint32_t)((r0 * 136 + cb) << 1)) =
                    __floats2half2_rn(a[0], a[1]);
                *(__half2*)(smc + R_OFF + (uint32_t)(((r0 + 8) * 136 + cb) << 1)) =
                    __floats2half2_rn(a[2], a[3]);
            }
        }
    }

    // ================= layer 1: rs = relu(t0 @ W1 + b1)  (K=384, N=384) =====
    {
        float acc[24][4];
#pragma unroll
        for (int x = 0; x < 24; x++)
#pragma unroll
            for (int y = 0; y < 4; y++) acc[x][y] = 0.f;
        run_gemm<12, 48, 8>(g_w1h, HID, HID, sb + T0_OFF + m0 * 784, 392,
                            colg * 96, sb + B0_OFF, sb + B1_OFF, acc, tid, lane);
#pragma unroll
        for (int mg = 0; mg < 2; mg++) {
            const int r0 = rbase + (mg << 4);
#pragma unroll
            for (int ng = 0; ng < 12; ng++) {
                const int cb = colg * 96 + (ng << 3) + ((lane & 3) << 1);
                float2 bb = *(const float2*)(b_t1v + cb);
                const float* a = acc[mg * 12 + ng];
                *(__half2*)(smc + RS_OFF + (uint32_t)((r0 * 392 + cb) << 1)) =
                    __floats2half2_rn(fmaxf(a[0] + bb.x, 0.f),
                                      fmaxf(a[1] + bb.y, 0.f));
                *(__half2*)(smc + RS_OFF + (uint32_t)(((r0 + 8) * 392 + cb) << 1)) =
                    __floats2half2_rn(fmaxf(a[2] + bb.x, 0.f),
                                      fmaxf(a[3] + bb.y, 0.f));
            }
        }
    }

    // ================= final: o = rs @ Wf + R + Pfi + Pfj  (K=384, N=128) ===
    {
        float acc[8][4];
#pragma unroll
        for (int mg = 0; mg < 2; mg++) {
            const int r0 = rbase + (mg << 4);
#pragma unroll
            for (int ng = 0; ng < 4; ng++) {
                const int cb = colg * 32 + (ng << 3) + ((lane & 3) << 1);
                float2 f0 = __half22float2(
                    *(__half2*)(smc + R_OFF + (uint32_t)((r0 * 136 + cb) << 1)));
                float2 f1 = __half22float2(
                    *(__half2*)(smc + R_OFF + (uint32_t)(((r0 + 8) * 136 + cb) << 1)));
                acc[mg * 4 + ng][0] = f0.x; acc[mg * 4 + ng][1] = f0.y;
                acc[mg * 4 + ng][2] = f1.x; acc[mg * 4 + ng][3] = f1.y;
            }
        }
        run_gemm<4, 48, 8>(g_wfh, HID, EOUT, sb + RS_OFF + m0 * 784, 392,
                           colg * 32, sb + B0_OFF, sb + B1_OFF, acc, tid, lane);
        // epilogue -> o_buf (fp32, overlays E+R — R fully consumed above)
        const float* pfi = g_pfi + (size_t)i * EOUT;
        const float* pfj = g_pfj + (size_t)j0 * EOUT;
        float* ob = (float*)(smc + O_OFF);
#pragma unroll
        for (int mg = 0; mg < 2; mg++) {
            const int r0 = rbase + (mg << 4);
#pragma unroll
            for (int ng = 0; ng < 4; ng++) {
                const int cb = colg * 32 + (ng << 3) + ((lane & 3) << 1);
                float2 fi  = *(const float2*)(pfi + cb);
                float2 fj0 = *(const float2*)(pfj + (size_t)r0 * EOUT + cb);
                float2 fj1 = *(const float2*)(pfj + (size_t)(r0 + 8) * EOUT + cb);
                const float* a = acc[mg * 4 + ng];
                float2 v0 = { a[0] + fi.x + fj0.x, a[1] + fi.y + fj0.y };
                float2 v1 = { a[2] + fi.x + fj1.x, a[3] + fi.y + fj1.y };
                *(float2*)(ob + r0 * 132 + cb)       = v0;
                *(float2*)(ob + (r0 + 8) * 132 + cb) = v1;
            }
        }
    }
    __syncthreads();

    // ---- LayerNorm over 128 + store: warp w owns rows w*8 .. w*8+7 ----
    {
        const float* ob = (const float*)(smc + O_OFF);
        const float g0 = ln_g[lane],      b0 = ln_b[lane];
        const float g1 = ln_g[lane + 32], b1 = ln_b[lane + 32];
        const float g2 = ln_g[lane + 64], b2 = ln_b[lane + 64];
        const float g3 = ln_g[lane + 96], b3 = ln_b[lane + 96];
#pragma unroll
        for (int rr = 0; rr < 8; rr++) {
            const int m = w * 8 + rr;
            const float* row = ob + m * 132;
            float v0 = row[lane], v1 = row[lane + 32];
            float v2 = row[lane + 64], v3 = row[lane + 96];
            float s = v0 + v1 + v2 + v3;
#pragma unroll
            for (int off = 16; off; off >>= 1)
                s += __shfl_xor_sync(0xffffffffu, s, off);
            const float mu = s * (1.0f / 128.0f);
            float d0 = v0 - mu, d1 = v1 - mu, d2 = v2 - mu, d3 = v3 - mu;
            float q = d0 * d0 + d1 * d1 + d2 * d2 + d3 * d3;
#pragma unroll
            for (int off = 16; off; off >>= 1)
                q += __shfl_xor_sync(0xffffffffu, q, off);
            const float rstd = rsqrtf(q * (1.0f / 128.0f) + 1e-5f);
            float* op = out + (size_t)(i * NSEQ + j0 + m) * EOUT;
            op[lane]      = d0 * rstd * g0 + b0;
            op[lane + 32] = d1 * rstd * g1 + b1;
            op[lane + 64] = d2 * rstd * g2 + b2;
            op[lane + 96] = d3 * rstd * g3 + b3;
        }
    }
}

// ---------------------------------------------------------------------------
extern "C" void kernel_launch(void* const* d_in, const int* in_sizes, int n_in,
                              void* d_out, int out_size) {
    const float* node   = (const float*)d_in[0];
    const float* edge   = (const float*)d_in[1];
    const float* w_init = (const float*)d_in[2];
    const float* b_init = (const float*)d_in[3];
    const float* w_t0   = (const float*)d_in[4];
    const float* b_t0   = (const float*)d_in[5];
    const float* w_t1   = (const float*)d_in[6];
    const float* b_t1   = (const float*)d_in[7];
    const float* w_fin  = (const float*)d_in[8];
    const float* b_fin  = (const float*)d_in[9];
    const float* ln_g   = (const float*)d_in[10];
    const float* ln_b   = (const float*)d_in[11];
    float* out = (float*)d_out;
    (void)in_sizes; (void)n_in; (void)out_size;

    cudaFuncSetAttribute(fusedh,
                         cudaFuncAttributeMaxDynamicSharedMemorySize, SMEMSZ);

    packh_kernel<<<256, 256>>>(w_t0, w_t1, w_fin);
    nb_kernel<<<NSEQ, 128>>>(node, w_init, b_init);
    pre_kernel<<<NSEQ, HID>>>(w_t0, b_t0, w_fin, b_fin);
    fusedh<<<4096, 256, SMEMSZ>>>(edge, b_t1, ln_g, ln_b, out);
}